// round 14
// baseline (speedup 1.0000x reference)
#include <cuda_runtime.h>
#include <cuda_bf16.h>
#include <cstdint>

#define BATCH 512
#define TSTEPS 1024
#define IDIM 64
#define HDIM 128
#define NB 8                        // batches per CTA (= mma N)
#define NCTA (BATCH / NB)           // 64 CTAs
#define TILE_T 8                    // steps per x staging tile
#define KCH 12                      // 8 h-chunks + 4 x-chunks of k16

// Pre-split x, packed in the exact B-fragment word layout:
// per (cta, t): 576 words = [split(2)][b(8)][36 words], row stride 36 words
// (36 mod 32 = 4 -> B-frag LDS bank = 4b+q, conflict-free).
__device__ uint32_t g_xprep[(size_t)NCTA * TSTEPS * 576];

__device__ __forceinline__ float tanh_ap(float x) {
    float y; asm("tanh.approx.f32 %0, %1;" : "=f"(y) : "f"(x)); return y;
}
__device__ __forceinline__ uint32_t pk2(float v0, float v1) {
    __nv_bfloat162 t = __floats2bfloat162_rn(v0, v1);   // .x = v0 (low half)
    return *(uint32_t*)&t;
}
// m16n8k16 row.col f32.bf16.bf16.f32 — baseline PTX (sm_80+).
__device__ __forceinline__ void mma_bf16(float* c, const uint32_t* a,
                                         uint32_t b0, uint32_t b1) {
    asm volatile(
        "mma.sync.aligned.m16n8k16.row.col.f32.bf16.bf16.f32 "
        "{%0,%1,%2,%3}, {%4,%5,%6,%7}, {%8,%9}, {%0,%1,%2,%3};"
        : "+f"(c[0]), "+f"(c[1]), "+f"(c[2]), "+f"(c[3])
        : "r"(a[0]), "r"(a[1]), "r"(a[2]), "r"(a[3]), "r"(b0), "r"(b1));
}
__device__ __forceinline__ uint32_t smem_u32(const void* p) {
    uint32_t a;
    asm("{ .reg .u64 t; cvta.to.shared.u64 t, %1; cvt.u32.u64 %0, t; }" : "=r"(a) : "l"(p));
    return a;
}
#define CPASYNC16(d, s) asm volatile("cp.async.cg.shared.global [%0], [%1], 16;" :: "r"(d), "l"(s) : "memory")
#define CP_COMMIT()     asm volatile("cp.async.commit_group;" ::: "memory")
#define CP_WAIT0()      asm volatile("cp.async.wait_group 0;" ::: "memory")

// ---------------------------------------------------------------------------
// Prep: split x into bf16 hi/lo pairs, packed as B-operand words.
// One warp per (cta, t); lane handles i = 2*lane, 2*lane+1.
// ---------------------------------------------------------------------------
__global__ void xprep_kernel(const float* __restrict__ x) {
    int gw   = (blockIdx.x * blockDim.x + threadIdx.x) >> 5;
    int lane = threadIdx.x & 31;
    int nw   = (gridDim.x * blockDim.x) >> 5;
    for (int task = gw; task < NCTA * TSTEPS; task += nw) {
        int c = task >> 10;
        int t = task & 1023;
        uint32_t* outw = g_xprep + (size_t)task * 576;
        #pragma unroll
        for (int b = 0; b < NB; b++) {
            float2 v = *(const float2*)(x + ((size_t)(c * NB + b) * TSTEPS + t) * IDIM + 2 * lane);
            __nv_bfloat162 hi = __floats2bfloat162_rn(v.x, v.y);
            float l0 = v.x - __bfloat162float(hi.x);
            float l1 = v.y - __bfloat162float(hi.y);
            outw[b * 36 + lane]       = *(uint32_t*)&hi;      // hi split
            outw[288 + b * 36 + lane] = pk2(l0, l1);          // lo split
        }
    }
}

// ---------------------------------------------------------------------------
// Main: mma.sync recurrence. 64 CTAs x 256 threads (8 warps), 8 batches/CTA.
// Warp w owns j rows [16w, 16w+16). A-fragments of W' = [W_hh | W_ih]
// (bf16 hi+lo) in 96 registers, loaded once.
// SIX accumulator chains for the h-MMAs (chain = product*2 + kc parity) so
// same-chain dep distance is 6 issue slots (covers HMMA latency).
// The 12 x-MMAs for step t+1 are issued in the barrier tail (h-independent),
// accumulating into freshly zeroed chains c0..c2.
// h in shared: [ping][split][b][68 words] (68 mod 32 = 4 -> bank 4b+q).
// ---------------------------------------------------------------------------
__global__ void __launch_bounds__(256, 1) rnn_mma(
    const float* __restrict__ W_ih,
    const float* __restrict__ W_hh,
    const float* __restrict__ b_ih,
    const float* __restrict__ b_hh,
    const float* __restrict__ fc_w,
    const float* __restrict__ fc_b,
    float* __restrict__ out)
{
    __shared__ uint32_t hsh[2][2][NB][68];            // 8704 B
    __shared__ uint32_t xsh[2][TILE_T][2][NB][36];    // 36864 B

    const int tid  = threadIdx.x;
    const int w    = tid >> 5, lane = tid & 31;
    const int q    = lane & 3;          // quad col
    const int rh   = lane >> 2;         // 0..7
    const int j0   = 16 * w + rh;       // accum rows j0, j0+8
    const int bN   = rh;                // B-frag batch col
    const int c    = blockIdx.x;

    // ---- A fragments (weights), hi + lo splits ----
    uint32_t wa[KCH][4], wl[KCH][4];
    #pragma unroll
    for (int kc = 0; kc < KCH; kc++) {
        #pragma unroll
        for (int rr = 0; rr < 4; rr++) {
            int row = j0 + (rr & 1) * 8;
            int col = kc * 16 + q * 2 + (rr >> 1) * 8;
            const float* src = (kc < 8) ? (W_hh + (size_t)row * HDIM + col)
                                        : (W_ih + (size_t)row * IDIM + (col - 128));
            float v0 = src[0], v1 = src[1];
            __nv_bfloat162 hi = __floats2bfloat162_rn(v0, v1);
            wa[kc][rr] = *(uint32_t*)&hi;
            wl[kc][rr] = pk2(v0 - __bfloat162float(hi.x), v1 - __bfloat162float(hi.y));
        }
    }
    const float bias_a = b_ih[j0] + b_hh[j0];
    const float bias_b = b_ih[j0 + 8] + b_hh[j0 + 8];

    // ---- h0 = 0 ----
    for (int i = tid; i < 2 * 2 * NB * 68; i += 256) (&hsh[0][0][0][0])[i] = 0;

    const uint32_t xs0 = smem_u32(&xsh[0][0][0][0][0]);

    // ---- stage x tile 0 ----
    {
        const uint32_t* src = g_xprep + (size_t)c * TSTEPS * 576;
        #pragma unroll
        for (int r = 0; r < 5; r++) {
            int idx = tid + 256 * r;
            if (idx < 1152) CPASYNC16(xs0 + idx * 16, src + idx * 4);
        }
    }
    CP_COMMIT();
    CP_WAIT0();
    __syncthreads();

    // 6 accumulator chains: c[0..2] also receive the x products
    float acc[6][4];
    #pragma unroll
    for (int ch = 0; ch < 6; ch++)
        #pragma unroll
        for (int e = 0; e < 4; e++) acc[ch][e] = 0.f;

    // x-MMAs for t = 0
    #pragma unroll
    for (int xc = 0; xc < 4; xc++) {
        const uint32_t* xbH = &xsh[0][0][0][bN][0];
        const uint32_t* xbL = &xsh[0][0][1][bN][0];
        uint32_t b0h = xbH[xc * 8 + q], b1h = xbH[xc * 8 + q + 4];
        uint32_t b0l = xbL[xc * 8 + q], b1l = xbL[xc * 8 + q + 4];
        mma_bf16(acc[0], wa[8 + xc], b0h, b1h);
        mma_bf16(acc[1], wa[8 + xc], b0l, b1l);
        mma_bf16(acc[2], wl[8 + xc], b0h, b1h);
    }

    float h4[4] = {0.f, 0.f, 0.f, 0.f};
    int par = 0, sbuf = 0;

    #pragma unroll 1
    for (int tile = 0; tile < TSTEPS / TILE_T; tile++) {
        // prefetch next x tile
        if (tile + 1 < TSTEPS / TILE_T) {
            const uint32_t* src = g_xprep + ((size_t)c * TSTEPS + (tile + 1) * TILE_T) * 576;
            uint32_t dst = xs0 + (uint32_t)(sbuf ^ 1) * 18432u;
            #pragma unroll
            for (int r = 0; r < 5; r++) {
                int idx = tid + 256 * r;
                if (idx < 1152) CPASYNC16(dst + idx * 16, src + idx * 4);
            }
        }
        CP_COMMIT();

        #pragma unroll 1
        for (int u = 0; u < TILE_T; u++) {
            // ---- h-MMAs (24) over 6 chains ----
            const uint32_t* hbH = &hsh[par][0][bN][0];
            const uint32_t* hbL = &hsh[par][1][bN][0];
            #pragma unroll
            for (int kc = 0; kc < 8; kc++) {
                int e = kc & 1;
                uint32_t b0h = hbH[kc * 8 + q], b1h = hbH[kc * 8 + q + 4];
                uint32_t b0l = hbL[kc * 8 + q], b1l = hbL[kc * 8 + q + 4];
                mma_bf16(acc[e],     wa[kc], b0h, b1h);
                mma_bf16(acc[2 + e], wa[kc], b0l, b1l);
                mma_bf16(acc[4 + e], wl[kc], b0h, b1h);
            }

            // ---- epilogue: sum chains, bias, tanh ----
            #pragma unroll
            for (int e = 0; e < 4; e++) {
                float s = ((acc[0][e] + acc[1][e]) + (acc[2][e] + acc[3][e]))
                        + (acc[4][e] + acc[5][e]);
                h4[e] = tanh_ap(s + ((e < 2) ? bias_a : bias_b));
            }

            // store h_{t+1} (hi/lo) into the other h buffer, B layout
            {
                uint16_t* dh = (uint16_t*)&hsh[par ^ 1][0][0][0];  // 136 halves/row
                uint16_t* dl = (uint16_t*)&hsh[par ^ 1][1][0][0];
                int n0 = 2 * q;
                #pragma unroll
                for (int e = 0; e < 4; e++) {
                    int jj = j0 + (e >> 1) * 8;
                    int nn = n0 + (e & 1);
                    __nv_bfloat16 hh = __float2bfloat16_rn(h4[e]);
                    __nv_bfloat16 hl = __float2bfloat16_rn(h4[e] - __bfloat162float(hh));
                    dh[nn * 136 + jj] = *(uint16_t*)&hh;
                    dl[nn * 136 + jj] = *(uint16_t*)&hl;
                }
            }

            // ---- zero chains; x-MMAs for t+1 fill the barrier tail ----
            #pragma unroll
            for (int ch = 0; ch < 6; ch++)
                #pragma unroll
                for (int e = 0; e < 4; e++) acc[ch][e] = 0.f;

            if (u < TILE_T - 1) {
                const uint32_t* xbH = &xsh[sbuf][u + 1][0][bN][0];
                const uint32_t* xbL = &xsh[sbuf][u + 1][1][bN][0];
                #pragma unroll
                for (int xc = 0; xc < 4; xc++) {
                    uint32_t b0h = xbH[xc * 8 + q], b1h = xbH[xc * 8 + q + 4];
                    uint32_t b0l = xbL[xc * 8 + q], b1l = xbL[xc * 8 + q + 4];
                    mma_bf16(acc[0], wa[8 + xc], b0h, b1h);
                    mma_bf16(acc[1], wa[8 + xc], b0l, b1l);
                    mma_bf16(acc[2], wl[8 + xc], b0h, b1h);
                }
            }
            __syncthreads();
            par ^= 1;
        }

        // tile boundary: wait for the prefetched buffer, then x-MMAs for its
        // first step (t+1 = (tile+1)*TILE_T), which were skipped above.
        CP_WAIT0();
        __syncthreads();
        if (tile + 1 < TSTEPS / TILE_T) {
            const uint32_t* xbH = &xsh[sbuf ^ 1][0][0][bN][0];
            const uint32_t* xbL = &xsh[sbuf ^ 1][0][1][bN][0];
            #pragma unroll
            for (int xc = 0; xc < 4; xc++) {
                uint32_t b0h = xbH[xc * 8 + q], b1h = xbH[xc * 8 + q + 4];
                uint32_t b0l = xbL[xc * 8 + q], b1l = xbL[xc * 8 + q + 4];
                mma_bf16(acc[0], wa[8 + xc], b0h, b1h);
                mma_bf16(acc[1], wa[8 + xc], b0l, b1l);
                mma_bf16(acc[2], wl[8 + xc], b0h, b1h);
            }
        }
        sbuf ^= 1;
    }

    // ---- fc + sigmoid epilogue (reuse x staging as fp32 scratch) ----
    {
        float* hf = (float*)xsh;                 // [n][132] floats
        int n0 = 2 * q;
        hf[n0 * 132 + j0]           = h4[0];
        hf[(n0 + 1) * 132 + j0]     = h4[1];
        hf[n0 * 132 + j0 + 8]       = h4[2];
        hf[(n0 + 1) * 132 + j0 + 8] = h4[3];
        __syncthreads();
        if (w < NB) {
            float sum = 0.f;
            #pragma unroll
            for (int i = lane; i < HDIM; i += 32)
                sum += hf[w * 132 + i] * fc_w[i];
            #pragma unroll
            for (int o = 16; o > 0; o >>= 1)
                sum += __shfl_xor_sync(0xffffffffu, sum, o);
            if (lane == 0)
                out[c * NB + w] = 1.f / (1.f + __expf(-(sum + fc_b[0])));
        }
    }
}

// ---------------------------------------------------------------------------
extern "C" void kernel_launch(void* const* d_in, const int* in_sizes, int n_in,
                              void* d_out, int out_size)
{
    const float* x    = (const float*)d_in[0];
    const float* W_ih = (const float*)d_in[1];
    const float* W_hh = (const float*)d_in[2];
    const float* b_ih = (const float*)d_in[3];
    const float* b_hh = (const float*)d_in[4];
    const float* fc_w = (const float*)d_in[5];
    const float* fc_b = (const float*)d_in[6];
    float* out = (float*)d_out;

    xprep_kernel<<<512, 256>>>(x);
    rnn_mma<<<NCTA, 256>>>(W_ih, W_hh, b_ih, b_hh, fc_w, fc_b, out);
}

// round 15
// speedup vs baseline: 1.1340x; 1.1340x over previous
#include <cuda_runtime.h>
#include <cuda_bf16.h>
#include <cstdint>

#define BATCH 512
#define TSTEPS 1024
#define IDIM 64
#define HDIM 128
#define NB 8                        // batches per CTA (= mma N)
#define NCTA (BATCH / NB)           // 64 CTAs
#define TILE_T 8                    // steps per x staging tile
#define KCH 12                      // 8 h-chunks + 4 x-chunks of k16

// Pre-split x, packed in the exact B-fragment word layout:
// per (cta, t): 576 words = [split(2)][b(8)][36 words], row stride 36 words
// (36 mod 32 = 4 -> B-frag LDS bank = 4b+q, conflict-free).
__device__ uint32_t g_xprep[(size_t)NCTA * TSTEPS * 576];

__device__ __forceinline__ float tanh_ap(float x) {
    float y; asm("tanh.approx.f32 %0, %1;" : "=f"(y) : "f"(x)); return y;
}
__device__ __forceinline__ uint32_t pk2(float v0, float v1) {
    __nv_bfloat162 t = __floats2bfloat162_rn(v0, v1);   // .x = v0 (low half)
    return *(uint32_t*)&t;
}
// m16n8k16 row.col f32.bf16.bf16.f32 — baseline PTX (sm_80+).
__device__ __forceinline__ void mma_bf16(float* c, const uint32_t* a,
                                         uint32_t b0, uint32_t b1) {
    asm volatile(
        "mma.sync.aligned.m16n8k16.row.col.f32.bf16.bf16.f32 "
        "{%0,%1,%2,%3}, {%4,%5,%6,%7}, {%8,%9}, {%0,%1,%2,%3};"
        : "+f"(c[0]), "+f"(c[1]), "+f"(c[2]), "+f"(c[3])
        : "r"(a[0]), "r"(a[1]), "r"(a[2]), "r"(a[3]), "r"(b0), "r"(b1));
}
__device__ __forceinline__ uint32_t smem_u32(const void* p) {
    uint32_t a;
    asm("{ .reg .u64 t; cvta.to.shared.u64 t, %1; cvt.u32.u64 %0, t; }" : "=r"(a) : "l"(p));
    return a;
}
#define CPASYNC16(d, s) asm volatile("cp.async.cg.shared.global [%0], [%1], 16;" :: "r"(d), "l"(s) : "memory")
#define CP_COMMIT()     asm volatile("cp.async.commit_group;" ::: "memory")
#define CP_WAIT0()      asm volatile("cp.async.wait_group 0;" ::: "memory")

// ---------------------------------------------------------------------------
// Prep: split x into bf16 hi/lo pairs, packed as B-operand words.
// One warp per (cta, t); lane handles i = 2*lane, 2*lane+1.
// ---------------------------------------------------------------------------
__global__ void xprep_kernel(const float* __restrict__ x) {
    int gw   = (blockIdx.x * blockDim.x + threadIdx.x) >> 5;
    int lane = threadIdx.x & 31;
    int nw   = (gridDim.x * blockDim.x) >> 5;
    for (int task = gw; task < NCTA * TSTEPS; task += nw) {
        int c = task >> 10;
        int t = task & 1023;
        uint32_t* outw = g_xprep + (size_t)task * 576;
        #pragma unroll
        for (int b = 0; b < NB; b++) {
            float2 v = *(const float2*)(x + ((size_t)(c * NB + b) * TSTEPS + t) * IDIM + 2 * lane);
            __nv_bfloat162 hi = __floats2bfloat162_rn(v.x, v.y);
            float l0 = v.x - __bfloat162float(hi.x);
            float l1 = v.y - __bfloat162float(hi.y);
            outw[b * 36 + lane]       = *(uint32_t*)&hi;      // hi split
            outw[288 + b * 36 + lane] = pk2(l0, l1);          // lo split
        }
    }
}

// ---------------------------------------------------------------------------
// Main: mma.sync recurrence. 64 CTAs x 256 threads (8 warps), 8 batches/CTA.
// Warp w owns j rows [16w, 16w+16): its A-fragments of W' = [W_hh | W_ih]
// (bf16 hi+lo) live in 96 registers, loaded once.
// Per step: z = Whi*vhi + Whi*vlo + Wlo*vhi via 36 HMMA over SIX accumulator
// chains (chain = product*2 + kc parity -> dep depth 6 instead of 12), same
// program order as the proven R13 kernel. One __syncthreads per step; the
// tile-boundary barrier is merged into the last step's barrier.
// h in shared: [ping][split][b][68 words] (68 mod 32 = 4 -> bank 4b+q).
// ---------------------------------------------------------------------------
__global__ void __launch_bounds__(256) rnn_mma(
    const float* __restrict__ W_ih,
    const float* __restrict__ W_hh,
    const float* __restrict__ b_ih,
    const float* __restrict__ b_hh,
    const float* __restrict__ fc_w,
    const float* __restrict__ fc_b,
    float* __restrict__ out)
{
    __shared__ uint32_t hsh[2][2][NB][68];            // 8704 B
    __shared__ uint32_t xsh[2][TILE_T][2][NB][36];    // 36864 B

    const int tid  = threadIdx.x;
    const int w    = tid >> 5, lane = tid & 31;
    const int q    = lane & 3;          // quad col
    const int rh   = lane >> 2;         // 0..7
    const int j0   = 16 * w + rh;       // accum rows j0, j0+8
    const int bN   = rh;                // B-frag batch col
    const int c    = blockIdx.x;

    // ---- A fragments (weights), hi + lo splits ----
    uint32_t wa[KCH][4], wl[KCH][4];
    #pragma unroll
    for (int kc = 0; kc < KCH; kc++) {
        #pragma unroll
        for (int rr = 0; rr < 4; rr++) {
            int row = j0 + (rr & 1) * 8;
            int col = kc * 16 + q * 2 + (rr >> 1) * 8;
            const float* src = (kc < 8) ? (W_hh + (size_t)row * HDIM + col)
                                        : (W_ih + (size_t)row * IDIM + (col - 128));
            float v0 = src[0], v1 = src[1];
            __nv_bfloat162 hi = __floats2bfloat162_rn(v0, v1);
            wa[kc][rr] = *(uint32_t*)&hi;
            wl[kc][rr] = pk2(v0 - __bfloat162float(hi.x), v1 - __bfloat162float(hi.y));
        }
    }
    const float bias_a = b_ih[j0] + b_hh[j0];
    const float bias_b = b_ih[j0 + 8] + b_hh[j0 + 8];

    // ---- h0 = 0 ----
    for (int i = tid; i < 2 * 2 * NB * 68; i += 256) (&hsh[0][0][0][0])[i] = 0;

    const uint32_t xs0 = smem_u32(&xsh[0][0][0][0][0]);

    // ---- stage x tile 0 ----
    {
        const uint32_t* src = g_xprep + (size_t)c * TSTEPS * 576;
        #pragma unroll
        for (int r = 0; r < 5; r++) {
            int idx = tid + 256 * r;
            if (idx < 1152) CPASYNC16(xs0 + idx * 16, src + idx * 4);
        }
    }
    CP_COMMIT();
    CP_WAIT0();
    __syncthreads();

    float h4[4] = {0.f, 0.f, 0.f, 0.f};
    int par = 0, sbuf = 0;

    #pragma unroll 1
    for (int tile = 0; tile < TSTEPS / TILE_T; tile++) {
        // prefetch next x tile
        if (tile + 1 < TSTEPS / TILE_T) {
            const uint32_t* src = g_xprep + ((size_t)c * TSTEPS + (tile + 1) * TILE_T) * 576;
            uint32_t dst = xs0 + (uint32_t)(sbuf ^ 1) * 18432u;
            #pragma unroll
            for (int r = 0; r < 5; r++) {
                int idx = tid + 256 * r;
                if (idx < 1152) CPASYNC16(dst + idx * 16, src + idx * 4);
            }
        }
        CP_COMMIT();

        #pragma unroll 1
        for (int u = 0; u < TILE_T; u++) {
            const uint32_t* hbH = &hsh[par][0][bN][0];
            const uint32_t* hbL = &hsh[par][1][bN][0];
            const uint32_t* xbH = &xsh[sbuf][u][0][bN][0];
            const uint32_t* xbL = &xsh[sbuf][u][1][bN][0];

            // six accumulator chains: chain = product*2 + (kc & 1)
            float a0[4] = {0.f, 0.f, 0.f, 0.f};   // Whi*vhi, even kc
            float a1[4] = {0.f, 0.f, 0.f, 0.f};   // Whi*vhi, odd kc
            float a2[4] = {0.f, 0.f, 0.f, 0.f};   // Whi*vlo, even kc
            float a3[4] = {0.f, 0.f, 0.f, 0.f};   // Whi*vlo, odd kc
            float a4[4] = {0.f, 0.f, 0.f, 0.f};   // Wlo*vhi, even kc
            float a5[4] = {0.f, 0.f, 0.f, 0.f};   // Wlo*vhi, odd kc
            #pragma unroll
            for (int kc = 0; kc < KCH; kc++) {
                uint32_t b0h, b1h, b0l, b1l;
                if (kc < 8) {
                    b0h = hbH[kc * 8 + q];  b1h = hbH[kc * 8 + q + 4];
                    b0l = hbL[kc * 8 + q];  b1l = hbL[kc * 8 + q + 4];
                } else {
                    int xc = kc - 8;
                    b0h = xbH[xc * 8 + q];  b1h = xbH[xc * 8 + q + 4];
                    b0l = xbL[xc * 8 + q];  b1l = xbL[xc * 8 + q + 4];
                }
                if (kc & 1) {
                    mma_bf16(a1, wa[kc], b0h, b1h);
                    mma_bf16(a3, wa[kc], b0l, b1l);
                    mma_bf16(a5, wl[kc], b0h, b1h);
                } else {
                    mma_bf16(a0, wa[kc], b0h, b1h);
                    mma_bf16(a2, wa[kc], b0l, b1l);
                    mma_bf16(a4, wl[kc], b0h, b1h);
                }
            }

            #pragma unroll
            for (int e = 0; e < 4; e++) {
                float s = ((a0[e] + a1[e]) + (a2[e] + a3[e])) + (a4[e] + a5[e]);
                h4[e] = tanh_ap(s + ((e < 2) ? bias_a : bias_b));
            }

            // store h_{t+1} (hi/lo) into the other h buffer, B layout
            {
                uint16_t* dh = (uint16_t*)&hsh[par ^ 1][0][0][0];  // 136 halves/row
                uint16_t* dl = (uint16_t*)&hsh[par ^ 1][1][0][0];
                int n0 = 2 * q;
                #pragma unroll
                for (int e = 0; e < 4; e++) {
                    int jj = j0 + (e >> 1) * 8;
                    int nn = n0 + (e & 1);
                    __nv_bfloat16 hh = __float2bfloat16_rn(h4[e]);
                    __nv_bfloat16 hl = __float2bfloat16_rn(h4[e] - __bfloat162float(hh));
                    dh[nn * 136 + jj] = *(uint16_t*)&hh;
                    dl[nn * 136 + jj] = *(uint16_t*)&hl;
                }
            }
            // merged tile-boundary wait: own cp.asyncs complete, then the
            // per-step barrier makes them visible to all threads.
            if (u == TILE_T - 1) CP_WAIT0();
            __syncthreads();
            par ^= 1;
        }
        sbuf ^= 1;
    }

    // ---- fc + sigmoid epilogue (reuse x staging as fp32 scratch) ----
    {
        float* hf = (float*)xsh;                 // [n][132] floats
        int n0 = 2 * q;
        hf[n0 * 132 + j0]           = h4[0];
        hf[(n0 + 1) * 132 + j0]     = h4[1];
        hf[n0 * 132 + j0 + 8]       = h4[2];
        hf[(n0 + 1) * 132 + j0 + 8] = h4[3];
        __syncthreads();
        if (w < NB) {
            float sum = 0.f;
            #pragma unroll
            for (int i = lane; i < HDIM; i += 32)
                sum += hf[w * 132 + i] * fc_w[i];
            #pragma unroll
            for (int o = 16; o > 0; o >>= 1)
                sum += __shfl_xor_sync(0xffffffffu, sum, o);
            if (lane == 0)
                out[c * NB + w] = 1.f / (1.f + __expf(-(sum + fc_b[0])));
        }
    }
}

// ---------------------------------------------------------------------------
extern "C" void kernel_launch(void* const* d_in, const int* in_sizes, int n_in,
                              void* d_out, int out_size)
{
    const float* x    = (const float*)d_in[0];
    const float* W_ih = (const float*)d_in[1];
    const float* W_hh = (const float*)d_in[2];
    const float* b_ih = (const float*)d_in[3];
    const float* b_hh = (const float*)d_in[4];
    const float* fc_w = (const float*)d_in[5];
    const float* fc_b = (const float*)d_in[6];
    float* out = (float*)d_out;

    xprep_kernel<<<512, 256>>>(x);
    rnn_mma<<<NCTA, 256>>>(W_ih, W_hh, b_ih, b_hh, fc_w, fc_b, out);
}

// round 16
// speedup vs baseline: 1.1506x; 1.0147x over previous
#include <cuda_runtime.h>
#include <cuda_bf16.h>
#include <cstdint>

#define BATCH 512
#define TSTEPS 1024
#define IDIM 64
#define HDIM 128
#define NB 8                        // batches per CTA (= mma N)
#define NCTA (BATCH / NB)           // 64 CTAs
#define XTILE 8                     // steps per frag tile (gemm)
#define PTILE 4                     // steps per xp staging tile (rnn)

// Pre-split x, packed in B-fragment word layout: per (cta,t) 576 words.
__device__ uint32_t g_xprep[(size_t)NCTA * TSTEPS * 576];
// Precomputed input projection (+bias), fp32: [c][t][j(128)][b(8)].
__device__ float g_xp[(size_t)NCTA * TSTEPS * HDIM * NB];

__device__ __forceinline__ float tanh_ap(float x) {
    float y; asm("tanh.approx.f32 %0, %1;" : "=f"(y) : "f"(x)); return y;
}
__device__ __forceinline__ uint32_t pk2(float v0, float v1) {
    __nv_bfloat162 t = __floats2bfloat162_rn(v0, v1);
    return *(uint32_t*)&t;
}
// m16n8k16 row.col f32.bf16.bf16.f32 — baseline PTX (sm_80+).
__device__ __forceinline__ void mma_bf16(float* c, const uint32_t* a,
                                         uint32_t b0, uint32_t b1) {
    asm volatile(
        "mma.sync.aligned.m16n8k16.row.col.f32.bf16.bf16.f32 "
        "{%0,%1,%2,%3}, {%4,%5,%6,%7}, {%8,%9}, {%0,%1,%2,%3};"
        : "+f"(c[0]), "+f"(c[1]), "+f"(c[2]), "+f"(c[3])
        : "r"(a[0]), "r"(a[1]), "r"(a[2]), "r"(a[3]), "r"(b0), "r"(b1));
}
__device__ __forceinline__ uint32_t smem_u32(const void* p) {
    uint32_t a;
    asm("{ .reg .u64 t; cvta.to.shared.u64 t, %1; cvt.u32.u64 %0, t; }" : "=r"(a) : "l"(p));
    return a;
}
#define CPASYNC16(d, s) asm volatile("cp.async.cg.shared.global [%0], [%1], 16;" :: "r"(d), "l"(s) : "memory")
#define CP_COMMIT()     asm volatile("cp.async.commit_group;" ::: "memory")
#define CP_WAIT0()      asm volatile("cp.async.wait_group 0;" ::: "memory")

// ---------------------------------------------------------------------------
// Prep 1: split x into bf16 hi/lo, packed as B-operand words (proven kernel).
// ---------------------------------------------------------------------------
__global__ void xprep_kernel(const float* __restrict__ x) {
    int gw   = (blockIdx.x * blockDim.x + threadIdx.x) >> 5;
    int lane = threadIdx.x & 31;
    int nw   = (gridDim.x * blockDim.x) >> 5;
    for (int task = gw; task < NCTA * TSTEPS; task += nw) {
        int c = task >> 10;
        int t = task & 1023;
        uint32_t* outw = g_xprep + (size_t)task * 576;
        #pragma unroll
        for (int b = 0; b < NB; b++) {
            float2 v = *(const float2*)(x + ((size_t)(c * NB + b) * TSTEPS + t) * IDIM + 2 * lane);
            __nv_bfloat162 hi = __floats2bfloat162_rn(v.x, v.y);
            float l0 = v.x - __bfloat162float(hi.x);
            float l1 = v.y - __bfloat162float(hi.y);
            outw[b * 36 + lane]       = *(uint32_t*)&hi;
            outw[288 + b * 36 + lane] = pk2(l0, l1);
        }
    }
}

// ---------------------------------------------------------------------------
// Prep 2: xp = W_ih * x + (b_ih + b_hh), fp32, via 3-term bf16 mma.
// 256 CTAs: (c = bid>>2, 256-token slice = bid&3). Warp w -> rows 16w..16w+15.
// Per token-group (8 tokens): 12 HMMA over 3 chains.
// ---------------------------------------------------------------------------
__global__ void __launch_bounds__(256) xp_gemm(
    const float* __restrict__ W_ih,
    const float* __restrict__ b_ih,
    const float* __restrict__ b_hh)
{
    __shared__ uint32_t xfr[2][XTILE][2][NB][36];     // 36864 B

    const int tid  = threadIdx.x;
    const int w    = tid >> 5, lane = tid & 31;
    const int q    = lane & 3;
    const int rh   = lane >> 2;
    const int j0   = 16 * w + rh;
    const int bN   = rh;
    const int c    = blockIdx.x >> 2;
    const int t0   = (blockIdx.x & 3) * 256;

    uint32_t wa[4][4], wl[4][4];
    #pragma unroll
    for (int kc = 0; kc < 4; kc++) {
        #pragma unroll
        for (int rr = 0; rr < 4; rr++) {
            int row = j0 + (rr & 1) * 8;
            int col = kc * 16 + q * 2 + (rr >> 1) * 8;
            float v0 = W_ih[(size_t)row * IDIM + col];
            float v1 = W_ih[(size_t)row * IDIM + col + 1];
            __nv_bfloat162 hi = __floats2bfloat162_rn(v0, v1);
            wa[kc][rr] = *(uint32_t*)&hi;
            wl[kc][rr] = pk2(v0 - __bfloat162float(hi.x), v1 - __bfloat162float(hi.y));
        }
    }
    const float bias_a = b_ih[j0] + b_hh[j0];
    const float bias_b = b_ih[j0 + 8] + b_hh[j0 + 8];

    const uint32_t xs0 = smem_u32(&xfr[0][0][0][0][0]);

    // stage tile 0
    {
        const uint32_t* src = g_xprep + ((size_t)c * TSTEPS + t0) * 576;
        #pragma unroll
        for (int r = 0; r < 5; r++) {
            int idx = tid + 256 * r;
            if (idx < 1152) CPASYNC16(xs0 + idx * 16, src + idx * 4);
        }
    }
    CP_COMMIT();
    CP_WAIT0();
    __syncthreads();

    int sbuf = 0;
    #pragma unroll 1
    for (int tile = 0; tile < 256 / XTILE; tile++) {
        if (tile + 1 < 256 / XTILE) {
            const uint32_t* src = g_xprep + ((size_t)c * TSTEPS + t0 + (tile + 1) * XTILE) * 576;
            uint32_t dst = xs0 + (uint32_t)(sbuf ^ 1) * 18432u;
            #pragma unroll
            for (int r = 0; r < 5; r++) {
                int idx = tid + 256 * r;
                if (idx < 1152) CPASYNC16(dst + idx * 16, src + idx * 4);
            }
        }
        CP_COMMIT();

        #pragma unroll 1
        for (int u = 0; u < XTILE; u++) {
            const uint32_t* xbH = &xfr[sbuf][u][0][bN][0];
            const uint32_t* xbL = &xfr[sbuf][u][1][bN][0];
            float a0[4] = {0.f, 0.f, 0.f, 0.f};
            float a1[4] = {0.f, 0.f, 0.f, 0.f};
            float a2[4] = {0.f, 0.f, 0.f, 0.f};
            #pragma unroll
            for (int kc = 0; kc < 4; kc++) {
                uint32_t b0h = xbH[kc * 8 + q], b1h = xbH[kc * 8 + q + 4];
                uint32_t b0l = xbL[kc * 8 + q], b1l = xbL[kc * 8 + q + 4];
                mma_bf16(a0, wa[kc], b0h, b1h);
                mma_bf16(a1, wa[kc], b0l, b1l);
                mma_bf16(a2, wl[kc], b0h, b1h);
            }
            int t = t0 + tile * XTILE + u;
            float* dst = g_xp + (((size_t)c * TSTEPS + t) * HDIM) * NB;
            float2 o01 = make_float2(a0[0] + a1[0] + a2[0] + bias_a,
                                     a0[1] + a1[1] + a2[1] + bias_a);
            float2 o23 = make_float2(a0[2] + a1[2] + a2[2] + bias_b,
                                     a0[3] + a1[3] + a2[3] + bias_b);
            *(float2*)(dst + (size_t)j0 * NB + 2 * q)       = o01;
            *(float2*)(dst + (size_t)(j0 + 8) * NB + 2 * q) = o23;
        }
        CP_WAIT0();
        __syncthreads();
        sbuf ^= 1;
    }
}

// ---------------------------------------------------------------------------
// Main: mma.sync recurrence, h-part only (24 HMMA/step over 6 chains).
// xp streamed from g_xp via cp.async (4-step tiles); bias folded into xp.
// xp smem layout [t][128][8] fp32 — LDS.64 at (j0, 2q) is conflict-free
// (bank = 8*rh + 2q, distinct within each 16-lane phase). No padding.
// ---------------------------------------------------------------------------
__global__ void __launch_bounds__(256) rnn_mma(
    const float* __restrict__ W_hh,
    const float* __restrict__ fc_w,
    const float* __restrict__ fc_b,
    float* __restrict__ out)
{
    __shared__ uint32_t hsh[2][2][NB][68];            // 8704 B
    __shared__ float    xpsh[2][PTILE][HDIM][NB];     // 32768 B

    const int tid  = threadIdx.x;
    const int w    = tid >> 5, lane = tid & 31;
    const int q    = lane & 3;
    const int rh   = lane >> 2;
    const int j0   = 16 * w + rh;
    const int bN   = rh;
    const int c    = blockIdx.x;

    // ---- A fragments: W_hh only (hi + lo), 64 regs ----
    uint32_t wa[8][4], wl[8][4];
    #pragma unroll
    for (int kc = 0; kc < 8; kc++) {
        #pragma unroll
        for (int rr = 0; rr < 4; rr++) {
            int row = j0 + (rr & 1) * 8;
            int col = kc * 16 + q * 2 + (rr >> 1) * 8;
            float v0 = W_hh[(size_t)row * HDIM + col];
            float v1 = W_hh[(size_t)row * HDIM + col + 1];
            __nv_bfloat162 hi = __floats2bfloat162_rn(v0, v1);
            wa[kc][rr] = *(uint32_t*)&hi;
            wl[kc][rr] = pk2(v0 - __bfloat162float(hi.x), v1 - __bfloat162float(hi.y));
        }
    }

    // ---- h0 = 0 ----
    for (int i = tid; i < 2 * 2 * NB * 68; i += 256) (&hsh[0][0][0][0])[i] = 0;

    const uint32_t xp0 = smem_u32(&xpsh[0][0][0][0]);

    // ---- stage xp tile 0 (4 steps x 1024 floats = 4 chunks/thread) ----
    {
        const float* src = g_xp + (size_t)c * TSTEPS * HDIM * NB;
        #pragma unroll
        for (int r = 0; r < 4; r++) {
            int idx = tid + 256 * r;          // 0..1023 chunks of 16B
            CPASYNC16(xp0 + idx * 16, src + idx * 4);
        }
    }
    CP_COMMIT();
    CP_WAIT0();
    __syncthreads();

    float h4[4] = {0.f, 0.f, 0.f, 0.f};
    int par = 0, sbuf = 0;

    #pragma unroll 1
    for (int tile = 0; tile < TSTEPS / PTILE; tile++) {
        if (tile + 1 < TSTEPS / PTILE) {
            const float* src = g_xp + ((size_t)c * TSTEPS + (tile + 1) * PTILE) * HDIM * NB;
            uint32_t dst = xp0 + (uint32_t)(sbuf ^ 1) * 16384u;
            #pragma unroll
            for (int r = 0; r < 4; r++) {
                int idx = tid + 256 * r;
                CPASYNC16(dst + idx * 16, src + idx * 4);
            }
        }
        CP_COMMIT();

        #pragma unroll 1
        for (int u = 0; u < PTILE; u++) {
            // xp loads first (no h dependency — latency hidden under MMAs)
            float2 xa = *(const float2*)&xpsh[sbuf][u][j0][2 * q];
            float2 xb = *(const float2*)&xpsh[sbuf][u][j0 + 8][2 * q];

            const uint32_t* hbH = &hsh[par][0][bN][0];
            const uint32_t* hbL = &hsh[par][1][bN][0];
            // six chains: product*2 + kc parity (dep depth 4)
            float a0[4] = {0.f, 0.f, 0.f, 0.f};
            float a1[4] = {0.f, 0.f, 0.f, 0.f};
            float a2[4] = {0.f, 0.f, 0.f, 0.f};
            float a3[4] = {0.f, 0.f, 0.f, 0.f};
            float a4[4] = {0.f, 0.f, 0.f, 0.f};
            float a5[4] = {0.f, 0.f, 0.f, 0.f};
            #pragma unroll
            for (int kc = 0; kc < 8; kc++) {
                uint32_t b0h = hbH[kc * 8 + q], b1h = hbH[kc * 8 + q + 4];
                uint32_t b0l = hbL[kc * 8 + q], b1l = hbL[kc * 8 + q + 4];
                if (kc & 1) {
                    mma_bf16(a1, wa[kc], b0h, b1h);
                    mma_bf16(a3, wa[kc], b0l, b1l);
                    mma_bf16(a5, wl[kc], b0h, b1h);
                } else {
                    mma_bf16(a0, wa[kc], b0h, b1h);
                    mma_bf16(a2, wa[kc], b0l, b1l);
                    mma_bf16(a4, wl[kc], b0h, b1h);
                }
            }

            float s0 = ((a0[0] + a1[0]) + (a2[0] + a3[0])) + (a4[0] + a5[0]);
            float s1 = ((a0[1] + a1[1]) + (a2[1] + a3[1])) + (a4[1] + a5[1]);
            float s2 = ((a0[2] + a1[2]) + (a2[2] + a3[2])) + (a4[2] + a5[2]);
            float s3 = ((a0[3] + a1[3]) + (a2[3] + a3[3])) + (a4[3] + a5[3]);
            h4[0] = tanh_ap(s0 + xa.x);
            h4[1] = tanh_ap(s1 + xa.y);
            h4[2] = tanh_ap(s2 + xb.x);
            h4[3] = tanh_ap(s3 + xb.y);

            // store h_{t+1} (hi/lo) into the other h buffer, B layout
            {
                uint16_t* dh = (uint16_t*)&hsh[par ^ 1][0][0][0];  // 136 halves/row
                uint16_t* dl = (uint16_t*)&hsh[par ^ 1][1][0][0];
                int n0 = 2 * q;
                #pragma unroll
                for (int e = 0; e < 4; e++) {
                    int jj = j0 + (e >> 1) * 8;
                    int nn = n0 + (e & 1);
                    __nv_bfloat16 hh = __float2bfloat16_rn(h4[e]);
                    __nv_bfloat16 hl = __float2bfloat16_rn(h4[e] - __bfloat162float(hh));
                    dh[nn * 136 + jj] = *(uint16_t*)&hh;
                    dl[nn * 136 + jj] = *(uint16_t*)&hl;
                }
            }
            if (u == PTILE - 1) CP_WAIT0();
            __syncthreads();
            par ^= 1;
        }
        sbuf ^= 1;
    }

    // ---- fc + sigmoid epilogue (reuse xp staging as fp32 scratch) ----
    {
        float* hf = (float*)xpsh;                // [n][132] floats
        int n0 = 2 * q;
        hf[n0 * 132 + j0]           = h4[0];
        hf[(n0 + 1) * 132 + j0]     = h4[1];
        hf[n0 * 132 + j0 + 8]       = h4[2];
        hf[(n0 + 1) * 132 + j0 + 8] = h4[3];
        __syncthreads();
        if (w < NB) {
            float sum = 0.f;
            #pragma unroll
            for (int i = lane; i < HDIM; i += 32)
                sum += hf[w * 132 + i] * fc_w[i];
            #pragma unroll
            for (int o = 16; o > 0; o >>= 1)
                sum += __shfl_xor_sync(0xffffffffu, sum, o);
            if (lane == 0)
                out[c * NB + w] = 1.f / (1.f + __expf(-(sum + fc_b[0])));
        }
    }
}

// ---------------------------------------------------------------------------
extern "C" void kernel_launch(void* const* d_in, const int* in_sizes, int n_in,
                              void* d_out, int out_size)
{
    const float* x    = (const float*)d_in[0];
    const float* W_ih = (const float*)d_in[1];
    const float* W_hh = (const float*)d_in[2];
    const float* b_ih = (const float*)d_in[3];
    const float* b_hh = (const float*)d_in[4];
    const float* fc_w = (const float*)d_in[5];
    const float* fc_b = (const float*)d_in[6];
    float* out = (float*)d_out;

    xprep_kernel<<<512, 256>>>(x);
    xp_gemm<<<NCTA * 4, 256>>>(W_ih, b_ih, b_hh);
    rnn_mma<<<NCTA, 256>>>(W_hh, fc_w, fc_b, out);
}

// round 17
// speedup vs baseline: 1.1946x; 1.0382x over previous
#include <cuda_runtime.h>
#include <cuda_bf16.h>
#include <cstdint>

#define BATCH 512
#define TSTEPS 1024
#define IDIM 64
#define HDIM 128
#define NB 8                        // batches per CTA (= mma N)
#define NCTA (BATCH / NB)           // 64 CTAs
#define XTILE 8                     // steps per raw-x staging tile (gemm)
#define PTILE 4                     // steps per xp staging tile (rnn)
#define XROWW 520                   // raw-x row stride per batch (words), ≡8 mod 32

// Precomputed input projection (+bias), fp32: [c][t][j(128)][b(8)].
__device__ float g_xp[(size_t)NCTA * TSTEPS * HDIM * NB];

__device__ __forceinline__ float tanh_ap(float x) {
    float y; asm("tanh.approx.f32 %0, %1;" : "=f"(y) : "f"(x)); return y;
}
__device__ __forceinline__ uint32_t pk2(float v0, float v1) {
    __nv_bfloat162 t = __floats2bfloat162_rn(v0, v1);
    return *(uint32_t*)&t;
}
// m16n8k16 row.col f32.bf16.bf16.f32 — baseline PTX (sm_80+).
__device__ __forceinline__ void mma_bf16(float* c, const uint32_t* a,
                                         uint32_t b0, uint32_t b1) {
    asm volatile(
        "mma.sync.aligned.m16n8k16.row.col.f32.bf16.bf16.f32 "
        "{%0,%1,%2,%3}, {%4,%5,%6,%7}, {%8,%9}, {%0,%1,%2,%3};"
        : "+f"(c[0]), "+f"(c[1]), "+f"(c[2]), "+f"(c[3])
        : "r"(a[0]), "r"(a[1]), "r"(a[2]), "r"(a[3]), "r"(b0), "r"(b1));
}
__device__ __forceinline__ uint32_t smem_u32(const void* p) {
    uint32_t a;
    asm("{ .reg .u64 t; cvta.to.shared.u64 t, %1; cvt.u32.u64 %0, t; }" : "=r"(a) : "l"(p));
    return a;
}
#define CPASYNC16(d, s) asm volatile("cp.async.cg.shared.global [%0], [%1], 16;" :: "r"(d), "l"(s) : "memory")
#define CP_COMMIT()     asm volatile("cp.async.commit_group;" ::: "memory")
#define CP_WAIT0()      asm volatile("cp.async.wait_group 0;" ::: "memory")

// ---------------------------------------------------------------------------
// xp = W_ih * x + (b_ih + b_hh), fp32, via 3-term bf16 mma — reads RAW x,
// converts to bf16 hi/lo B-fragments in registers (no packed intermediate).
// 256 CTAs: (c = bid>>2, 256-token slice = bid&3). Warp w -> rows 16w..16w+15.
// Raw x tile in shared: [buf][b][XROWW] fp32, XROWW=520 ≡ 8 (mod 32) makes
// the per-(kc) float2 reads bank-conflict-free (bank = 8b + 2q + 16kc).
// ---------------------------------------------------------------------------
__global__ void __launch_bounds__(256) xp_gemm(
    const float* __restrict__ x,
    const float* __restrict__ W_ih,
    const float* __restrict__ b_ih,
    const float* __restrict__ b_hh)
{
    __shared__ float xr[2][NB][XROWW];     // 33280 B

    const int tid  = threadIdx.x;
    const int w    = tid >> 5, lane = tid & 31;
    const int q    = lane & 3;
    const int rh   = lane >> 2;
    const int j0   = 16 * w + rh;
    const int bN   = rh;                   // B-fragment batch column
    const int c    = blockIdx.x >> 2;
    const int t0   = (blockIdx.x & 3) * 256;

    // A fragments of W_ih (hi + lo), 32 regs
    uint32_t wa[4][4], wl[4][4];
    #pragma unroll
    for (int kc = 0; kc < 4; kc++) {
        #pragma unroll
        for (int rr = 0; rr < 4; rr++) {
            int row = j0 + (rr & 1) * 8;
            int col = kc * 16 + q * 2 + (rr >> 1) * 8;
            float v0 = W_ih[(size_t)row * IDIM + col];
            float v1 = W_ih[(size_t)row * IDIM + col + 1];
            __nv_bfloat162 hi = __floats2bfloat162_rn(v0, v1);
            wa[kc][rr] = *(uint32_t*)&hi;
            wl[kc][rr] = pk2(v0 - __bfloat162float(hi.x), v1 - __bfloat162float(hi.y));
        }
    }
    const float bias_a = b_ih[j0] + b_hh[j0];
    const float bias_b = b_ih[j0 + 8] + b_hh[j0 + 8];

    const uint32_t xs0 = smem_u32(&xr[0][0][0]);

    // stage raw tile 0: 8b x 8t x 64i fp32 = 1024 16B-chunks (4/thread)
    #pragma unroll
    for (int r = 0; r < 4; r++) {
        int idx = tid + 256 * r;               // 0..1023
        int b = idx >> 7, tt = (idx >> 4) & 7, f = idx & 15;
        const float* src = x + ((size_t)(c * NB + b) * TSTEPS + t0 + tt) * IDIM + f * 4;
        CPASYNC16(xs0 + (uint32_t)(b * XROWW + tt * 64 + f * 4) * 4u, src);
    }
    CP_COMMIT();
    CP_WAIT0();
    __syncthreads();

    int sbuf = 0;
    #pragma unroll 1
    for (int tile = 0; tile < 256 / XTILE; tile++) {
        if (tile + 1 < 256 / XTILE) {
            uint32_t dst = xs0 + (uint32_t)(sbuf ^ 1) * (NB * XROWW * 4);
            #pragma unroll
            for (int r = 0; r < 4; r++) {
                int idx = tid + 256 * r;
                int b = idx >> 7, tt = (idx >> 4) & 7, f = idx & 15;
                const float* src = x + ((size_t)(c * NB + b) * TSTEPS
                                        + t0 + (tile + 1) * XTILE + tt) * IDIM + f * 4;
                CPASYNC16(dst + (uint32_t)(b * XROWW + tt * 64 + f * 4) * 4u, src);
            }
        }
        CP_COMMIT();

        #pragma unroll 1
        for (int u = 0; u < XTILE; u++) {
            const float* xb = &xr[sbuf][bN][u * 64];
            float a0[4] = {0.f, 0.f, 0.f, 0.f};
            float a1[4] = {0.f, 0.f, 0.f, 0.f};
            float a2[4] = {0.f, 0.f, 0.f, 0.f};
            #pragma unroll
            for (int kc = 0; kc < 4; kc++) {
                float2 vA = *(const float2*)(xb + 16 * kc + 2 * q);
                float2 vB = *(const float2*)(xb + 16 * kc + 2 * q + 8);
                __nv_bfloat162 hA = __floats2bfloat162_rn(vA.x, vA.y);
                __nv_bfloat162 hB = __floats2bfloat162_rn(vB.x, vB.y);
                uint32_t b0h = *(uint32_t*)&hA;
                uint32_t b1h = *(uint32_t*)&hB;
                uint32_t b0l = pk2(vA.x - __bfloat162float(hA.x), vA.y - __bfloat162float(hA.y));
                uint32_t b1l = pk2(vB.x - __bfloat162float(hB.x), vB.y - __bfloat162float(hB.y));
                mma_bf16(a0, wa[kc], b0h, b1h);
                mma_bf16(a1, wa[kc], b0l, b1l);
                mma_bf16(a2, wl[kc], b0h, b1h);
            }
            int t = t0 + tile * XTILE + u;
            float* dst = g_xp + (((size_t)c * TSTEPS + t) * HDIM) * NB;
            float2 o01 = make_float2(a0[0] + a1[0] + a2[0] + bias_a,
                                     a0[1] + a1[1] + a2[1] + bias_a);
            float2 o23 = make_float2(a0[2] + a1[2] + a2[2] + bias_b,
                                     a0[3] + a1[3] + a2[3] + bias_b);
            *(float2*)(dst + (size_t)j0 * NB + 2 * q)       = o01;
            *(float2*)(dst + (size_t)(j0 + 8) * NB + 2 * q) = o23;
        }
        CP_WAIT0();
        __syncthreads();
        sbuf ^= 1;
    }
}

// ---------------------------------------------------------------------------
// Main: mma.sync recurrence, h-part only (24 HMMA/step over 6 chains).
// xp streamed from g_xp via cp.async (4-step tiles); bias folded into xp;
// xp seeds accumulator chain a0 directly (C-operand layout matches (j,n)).
// xp smem layout [t][128][8] fp32 — LDS.64 at (j0, 2q) is conflict-free.
// ---------------------------------------------------------------------------
__global__ void __launch_bounds__(256) rnn_mma(
    const float* __restrict__ W_hh,
    const float* __restrict__ fc_w,
    const float* __restrict__ fc_b,
    float* __restrict__ out)
{
    __shared__ uint32_t hsh[2][2][NB][68];            // 8704 B
    __shared__ float    xpsh[2][PTILE][HDIM][NB];     // 32768 B

    const int tid  = threadIdx.x;
    const int w    = tid >> 5, lane = tid & 31;
    const int q    = lane & 3;
    const int rh   = lane >> 2;
    const int j0   = 16 * w + rh;
    const int bN   = rh;
    const int c    = blockIdx.x;

    // ---- A fragments: W_hh only (hi + lo), 64 regs ----
    uint32_t wa[8][4], wl[8][4];
    #pragma unroll
    for (int kc = 0; kc < 8; kc++) {
        #pragma unroll
        for (int rr = 0; rr < 4; rr++) {
            int row = j0 + (rr & 1) * 8;
            int col = kc * 16 + q * 2 + (rr >> 1) * 8;
            float v0 = W_hh[(size_t)row * HDIM + col];
            float v1 = W_hh[(size_t)row * HDIM + col + 1];
            __nv_bfloat162 hi = __floats2bfloat162_rn(v0, v1);
            wa[kc][rr] = *(uint32_t*)&hi;
            wl[kc][rr] = pk2(v0 - __bfloat162float(hi.x), v1 - __bfloat162float(hi.y));
        }
    }

    // ---- h0 = 0 ----
    for (int i = tid; i < 2 * 2 * NB * 68; i += 256) (&hsh[0][0][0][0])[i] = 0;

    const uint32_t xp0 = smem_u32(&xpsh[0][0][0][0]);

    // ---- stage xp tile 0 ----
    {
        const float* src = g_xp + (size_t)c * TSTEPS * HDIM * NB;
        #pragma unroll
        for (int r = 0; r < 4; r++) {
            int idx = tid + 256 * r;
            CPASYNC16(xp0 + idx * 16, src + idx * 4);
        }
    }
    CP_COMMIT();
    CP_WAIT0();
    __syncthreads();

    float h4[4] = {0.f, 0.f, 0.f, 0.f};
    int par = 0, sbuf = 0;

    #pragma unroll 1
    for (int tile = 0; tile < TSTEPS / PTILE; tile++) {
        if (tile + 1 < TSTEPS / PTILE) {
            const float* src = g_xp + ((size_t)c * TSTEPS + (tile + 1) * PTILE) * HDIM * NB;
            uint32_t dst = xp0 + (uint32_t)(sbuf ^ 1) * 16384u;
            #pragma unroll
            for (int r = 0; r < 4; r++) {
                int idx = tid + 256 * r;
                CPASYNC16(dst + idx * 16, src + idx * 4);
            }
        }
        CP_COMMIT();

        #pragma unroll 1
        for (int u = 0; u < PTILE; u++) {
            // xp loads first (no h dependency — latency hidden under MMAs)
            float2 xa = *(const float2*)&xpsh[sbuf][u][j0][2 * q];
            float2 xb = *(const float2*)&xpsh[sbuf][u][j0 + 8][2 * q];

            const uint32_t* hbH = &hsh[par][0][bN][0];
            const uint32_t* hbL = &hsh[par][1][bN][0];
            // six chains (chain = product*2 + kc parity); a0 seeded with xp
            float a0[4] = {xa.x, xa.y, xb.x, xb.y};
            float a1[4] = {0.f, 0.f, 0.f, 0.f};
            float a2[4] = {0.f, 0.f, 0.f, 0.f};
            float a3[4] = {0.f, 0.f, 0.f, 0.f};
            float a4[4] = {0.f, 0.f, 0.f, 0.f};
            float a5[4] = {0.f, 0.f, 0.f, 0.f};
            #pragma unroll
            for (int kc = 0; kc < 8; kc++) {
                uint32_t b0h = hbH[kc * 8 + q], b1h = hbH[kc * 8 + q + 4];
                uint32_t b0l = hbL[kc * 8 + q], b1l = hbL[kc * 8 + q + 4];
                if (kc & 1) {
                    mma_bf16(a1, wa[kc], b0h, b1h);
                    mma_bf16(a3, wa[kc], b0l, b1l);
                    mma_bf16(a5, wl[kc], b0h, b1h);
                } else {
                    mma_bf16(a0, wa[kc], b0h, b1h);
                    mma_bf16(a2, wa[kc], b0l, b1l);
                    mma_bf16(a4, wl[kc], b0h, b1h);
                }
            }

            #pragma unroll
            for (int e = 0; e < 4; e++) {
                float s = ((a0[e] + a1[e]) + (a2[e] + a3[e])) + (a4[e] + a5[e]);
                h4[e] = tanh_ap(s);
            }

            // store h_{t+1} (hi/lo) into the other h buffer, B layout
            {
                uint16_t* dh = (uint16_t*)&hsh[par ^ 1][0][0][0];  // 136 halves/row
                uint16_t* dl = (uint16_t*)&hsh[par ^ 1][1][0][0];
                int n0 = 2 * q;
                #pragma unroll
                for (int e = 0; e < 4; e++) {
                    int jj = j0 + (e >> 1) * 8;
                    int nn = n0 + (e & 1);
                    __nv_bfloat16 hh = __float2bfloat16_rn(h4[e]);
                    __nv_bfloat16 hl = __float2bfloat16_rn(h4[e] - __bfloat162float(hh));
                    dh[nn * 136 + jj] = *(uint16_t*)&hh;
                    dl[nn * 136 + jj] = *(uint16_t*)&hl;
                }
            }
            if (u == PTILE - 1) CP_WAIT0();
            __syncthreads();
            par ^= 1;
        }
        sbuf ^= 1;
    }

    // ---- fc + sigmoid epilogue (reuse xp staging as fp32 scratch) ----
    {
        float* hf = (float*)xpsh;                // [n][132] floats
        int n0 = 2 * q;
        hf[n0 * 132 + j0]           = h4[0];
        hf[(n0 + 1) * 132 + j0]     = h4[1];
        hf[n0 * 132 + j0 + 8]       = h4[2];
        hf[(n0 + 1) * 132 + j0 + 8] = h4[3];
        __syncthreads();
        if (w < NB) {
            float sum = 0.f;
            #pragma unroll
            for (int i = lane; i < HDIM; i += 32)
                sum += hf[w * 132 + i] * fc_w[i];
            #pragma unroll
            for (int o = 16; o > 0; o >>= 1)
                sum += __shfl_xor_sync(0xffffffffu, sum, o);
            if (lane == 0)
                out[c * NB + w] = 1.f / (1.f + __expf(-(sum + fc_b[0])));
        }
    }
}

// ---------------------------------------------------------------------------
extern "C" void kernel_launch(void* const* d_in, const int* in_sizes, int n_in,
                              void* d_out, int out_size)
{
    const float* x    = (const float*)d_in[0];
    const float* W_ih = (const float*)d_in[1];
    const float* W_hh = (const float*)d_in[2];
    const float* b_ih = (const float*)d_in[3];
    const float* b_hh = (const float*)d_in[4];
    const float* fc_w = (const float*)d_in[5];
    const float* fc_b = (const float*)d_in[6];
    float* out = (float*)d_out;

    xp_gemm<<<NCTA * 4, 256>>>(x, W_ih, b_ih, b_hh);
    rnn_mma<<<NCTA, 256>>>(W_hh, fc_w, fc_b, out);
}